// round 10
// baseline (speedup 1.0000x reference)
#include <cuda_runtime.h>
#include <math.h>

#define B_   8
#define C_   64
#define H_   256
#define W_   256
#define LD_  8
#define MEM_ 128
#define NROWS_ (B_ * W_)    // 2048
#define HCHUNK_ 64          // h rows per reduce/apply block
#define NQ_ (H_ / HCHUNK_)  // 4 chunks per plane
#define NBLK_ (B_ * C_ * NQ_)  // 2048
#define CQ_ (C_ * NQ_)      // 256 partial rows per batch
#define TP_  257            // padded transpose stride

// Scratch (allocation-free per harness rules)
__device__ float g_part[NBLK_ * W_];     // partials [b][c*4+q][w], coalesced (2 MB)
__device__ float g_gateT[B_ * C_ * W_];  // gate*mu, [bc][w] (0.5 MB)

// ---------------------------------------------------------------------------
// Kernel 1: partial sum over a 64-row h-chunk of one (b,c) plane.
// Coalesced float4 partial store (fast form, 23.3us / 74.9% DRAM measured).
// ---------------------------------------------------------------------------
__global__ __launch_bounds__(256) void reduce_h_partial_kernel(const float* __restrict__ x) {
    const int bcq = blockIdx.x;           // = (b*C+c)*4 + q  = b*256 + (c*4+q)
    const int t  = threadIdx.x;
    const int w4 = t & 63;                // float4 column 0..63
    const int hs = t >> 6;                // h-subgroup 0..3

    const float4* __restrict__ xp =
        (const float4*)(x + (size_t)(bcq >> 2) * (H_ * W_) +
                        (size_t)(bcq & (NQ_ - 1)) * HCHUNK_ * W_);

    float4 s0 = make_float4(0.f, 0.f, 0.f, 0.f);
    float4 s1 = make_float4(0.f, 0.f, 0.f, 0.f);

#pragma unroll
    for (int half = 0; half < 2; ++half) {
        float4 v[8];
#pragma unroll
        for (int k = 0; k < 8; ++k)
            v[k] = xp[(size_t)(hs + 4 * (half * 8 + k)) * (W_ / 4) + w4];
#pragma unroll
        for (int k = 0; k < 8; ++k) {
            if (k & 1) { s1.x += v[k].x; s1.y += v[k].y; s1.z += v[k].z; s1.w += v[k].w; }
            else       { s0.x += v[k].x; s0.y += v[k].y; s0.z += v[k].z; s0.w += v[k].w; }
        }
    }
    float4 s = make_float4(s0.x + s1.x, s0.y + s1.y, s0.z + s1.z, s0.w + s1.w);

    __shared__ float4 red[256];
    red[t] = s;
    __syncthreads();
    if (hs == 0) {
        float4 a = red[t], b1 = red[t + 64], c1 = red[t + 128], d = red[t + 192];
        a.x += b1.x + c1.x + d.x;
        a.y += b1.y + c1.y + d.y;
        a.z += b1.z + c1.z + d.z;
        a.w += b1.w + c1.w + d.w;
        __stcs(&((float4*)g_part)[(size_t)bcq * (W_ / 4) + w4], a);   // coalesced
    }
}

// ---------------------------------------------------------------------------
// Kernel 2: gating MLP + memory-bank attention. 256 blocks; block = (b, 8 w).
// Stages its 256(cq) x 8(w) partial tile through padded smem (transpose),
// then one warp per row runs the verified warp-per-row math.
// ---------------------------------------------------------------------------
__global__ __launch_bounds__(256) void gate_kernel(
    const float* __restrict__ w_sub, const float* __restrict__ b_sub,
    const float* __restrict__ w_up,  const float* __restrict__ b_up,
    const float* __restrict__ mb,    const float* __restrict__ mu)
{
    __shared__ float s_wsub[C_ * LD_];
    __shared__ float s_mb[LD_ * MEM_];
    __shared__ float s_wup[LD_ * C_];
    __shared__ float s_bsub[LD_];
    __shared__ float s_bup[C_];
    __shared__ float tile[8 * TP_];       // [wl][cq], padded

    const int tid = threadIdx.x;
    for (int i = tid; i < C_ * LD_;   i += blockDim.x) s_wsub[i] = w_sub[i];
    for (int i = tid; i < LD_ * MEM_; i += blockDim.x) s_mb[i]   = mb[i];
    for (int i = tid; i < LD_ * C_;   i += blockDim.x) s_wup[i]  = w_up[i];
    if (tid < LD_) s_bsub[tid] = b_sub[tid];
    if (tid < C_)  s_bup[tid]  = b_up[tid];

    const int b  = blockIdx.x >> 5;            // batch
    const int w8 = (blockIdx.x & 31) * 8;      // w slice start

    // Stage + transpose: 256 rows x 8 cols; thread (cq-group, wl).
#pragma unroll
    for (int it = 0; it < 8; ++it) {
        const int cq = (tid >> 3) + 32 * it;
        const int wl = tid & 7;
        tile[wl * TP_ + cq] = g_part[((size_t)b * CQ_ + cq) * W_ + w8 + wl];
    }
    __syncthreads();

    const float muv   = mu[0];
    const float inv_h = 1.0f / H_;
    const float scale = rsqrtf((float)LD_);

    const int wp   = tid >> 5;                 // warp -> row
    const int lane = tid & 31;
    const int w    = w8 + wp;
    const float* tr = tile + wp * TP_;

    // y[c] for c = lane, lane+32 (4 q-partials each, from smem)
    float yA = 0.f, yB = 0.f;
#pragma unroll
    for (int q = 0; q < NQ_; ++q) {
        yA += tr[lane * 4 + q];
        yB += tr[(lane + 32) * 4 + q];
    }
    yA *= inv_h; yB *= inv_h;

    float low[LD_];
#pragma unroll
    for (int j = 0; j < LD_; ++j) {
        float p = fmaf(yA, s_wsub[lane * LD_ + j],
                       yB * s_wsub[(lane + 32) * LD_ + j]);
#pragma unroll
        for (int off = 16; off > 0; off >>= 1)
            p += __shfl_xor_sync(0xffffffffu, p, off);
        low[j] = p + s_bsub[j];
    }

    float f1[4];
#pragma unroll
    for (int k = 0; k < 4; ++k) {
        const int m = lane + 32 * k;
        float acc = 0.f;
#pragma unroll
        for (int j = 0; j < LD_; ++j)
            acc = fmaf(low[j], s_mb[j * MEM_ + m], acc);
        f1[k] = acc * scale;
    }

    float mx = fmaxf(fmaxf(f1[0], f1[1]), fmaxf(f1[2], f1[3]));
#pragma unroll
    for (int off = 16; off > 0; off >>= 1)
        mx = fmaxf(mx, __shfl_xor_sync(0xffffffffu, mx, off));
    float e[4], sum = 0.f;
#pragma unroll
    for (int k = 0; k < 4; ++k) { e[k] = expf(f1[k] - mx); sum += e[k]; }
#pragma unroll
    for (int off = 16; off > 0; off >>= 1)
        sum += __shfl_xor_sync(0xffffffffu, sum, off);
    const float inv = 1.0f / sum;

    float y1[LD_];
#pragma unroll
    for (int j = 0; j < LD_; ++j) {
        float acc = 0.f;
#pragma unroll
        for (int k = 0; k < 4; ++k)
            acc = fmaf(e[k] * inv, s_mb[j * MEM_ + lane + 32 * k], acc);
#pragma unroll
        for (int off = 16; off > 0; off >>= 1)
            acc += __shfl_xor_sync(0xffffffffu, acc, off);
        y1[j] = acc;
    }

#pragma unroll
    for (int k = 0; k < 2; ++k) {
        const int c = lane + 32 * k;
        float acc = s_bup[c];
#pragma unroll
        for (int j = 0; j < LD_; ++j)
            acc = fmaf(y1[j], s_wup[j * C_ + c], acc);
        const float g = 1.0f / (1.0f + expf(-acc));
        g_gateT[(size_t)(b * C_ + c) * W_ + w] = g * muv;
    }
}

// ---------------------------------------------------------------------------
// Kernel 3: out = x * gate. Fixed float4 column per thread (gate = one reg).
// Batch-4 loads, minblocks 6 (occ fix). WRITE-THROUGH stores: out lines don't
// write-allocate in L2, protecting x residency from the reduce pass.
// ---------------------------------------------------------------------------
__global__ __launch_bounds__(256, 6) void apply_gate_kernel(
    const float* __restrict__ x, float* __restrict__ out)
{
    const int bcq = (NBLK_ - 1) - blockIdx.x;   // reverse order: L2 reuse
    const int bc  = bcq >> 2;
    const int q   = bcq & (NQ_ - 1);

    const int t   = threadIdx.x;
    const int w4  = t & 63;
    const int hs  = t >> 6;

    const float4 gv = __ldg(&((const float4*)(g_gateT + (size_t)bc * W_))[w4]);

    const size_t base = (size_t)bc * (H_ * W_) + (size_t)q * HCHUNK_ * W_;
    const float4* __restrict__ xp = (const float4*)(x + base);
    float4*       __restrict__ op = (float4*)(out + base);

#pragma unroll
    for (int quarter = 0; quarter < 4; ++quarter) {
        float4 v[4];
#pragma unroll
        for (int k = 0; k < 4; ++k)
            v[k] = __ldcs(&xp[(size_t)(hs + 4 * (quarter * 4 + k)) * (W_ / 4) + w4]);
#pragma unroll
        for (int k = 0; k < 4; ++k) {
            v[k].x *= gv.x; v[k].y *= gv.y; v[k].z *= gv.z; v[k].w *= gv.w;
            __stwt(&op[(size_t)(hs + 4 * (quarter * 4 + k)) * (W_ / 4) + w4], v[k]);
        }
    }
}

extern "C" void kernel_launch(void* const* d_in, const int* in_sizes, int n_in,
                              void* d_out, int out_size) {
    const float* x     = (const float*)d_in[0];
    const float* w_sub = (const float*)d_in[1];
    const float* b_sub = (const float*)d_in[2];
    const float* w_up  = (const float*)d_in[3];
    const float* b_up  = (const float*)d_in[4];
    const float* mb    = (const float*)d_in[5];
    const float* mu    = (const float*)d_in[6];
    float* out = (float*)d_out;

    reduce_h_partial_kernel<<<NBLK_, 256>>>(x);
    gate_kernel<<<256, 256>>>(w_sub, b_sub, w_up, b_up, mb, mu);
    apply_gate_kernel<<<NBLK_, 256>>>(x, out);
}

// round 11
// speedup vs baseline: 1.0389x; 1.0389x over previous
#include <cuda_runtime.h>
#include <math.h>

#define B_   8
#define C_   64
#define H_   256
#define W_   256
#define LD_  8
#define MEM_ 128
#define NROWS_ (B_ * W_)    // 2048
#define HCHUNK_ 64          // h rows per reduce/apply block
#define NQ_ (H_ / HCHUNK_)  // 4 chunks per plane
#define NBLK_ (B_ * C_ * NQ_)  // 2048
#define CQ_ (C_ * NQ_)      // 256 partial rows per batch
#define TP_  257            // padded transpose stride

// Scratch (allocation-free per harness rules)
__device__ float g_part[NBLK_ * W_];     // partials [b][c*4+q][w], coalesced (2 MB)
__device__ float g_gateT[B_ * C_ * W_];  // gate*mu, [bc][w] (0.5 MB)

// ---------------------------------------------------------------------------
// Kernel 1: partial sum over a 64-row h-chunk of one (b,c) plane.
// Coalesced float4 partial store (measured 23.2us / 75.5% DRAM).
// ---------------------------------------------------------------------------
__global__ __launch_bounds__(256) void reduce_h_partial_kernel(const float* __restrict__ x) {
    const int bcq = blockIdx.x;           // = b*256 + (c*4+q)
    const int t  = threadIdx.x;
    const int w4 = t & 63;                // float4 column 0..63
    const int hs = t >> 6;                // h-subgroup 0..3

    const float4* __restrict__ xp =
        (const float4*)(x + (size_t)(bcq >> 2) * (H_ * W_) +
                        (size_t)(bcq & (NQ_ - 1)) * HCHUNK_ * W_);

    float4 s0 = make_float4(0.f, 0.f, 0.f, 0.f);
    float4 s1 = make_float4(0.f, 0.f, 0.f, 0.f);

#pragma unroll
    for (int half = 0; half < 2; ++half) {
        float4 v[8];
#pragma unroll
        for (int k = 0; k < 8; ++k)
            v[k] = xp[(size_t)(hs + 4 * (half * 8 + k)) * (W_ / 4) + w4];
#pragma unroll
        for (int k = 0; k < 8; ++k) {
            if (k & 1) { s1.x += v[k].x; s1.y += v[k].y; s1.z += v[k].z; s1.w += v[k].w; }
            else       { s0.x += v[k].x; s0.y += v[k].y; s0.z += v[k].z; s0.w += v[k].w; }
        }
    }
    float4 s = make_float4(s0.x + s1.x, s0.y + s1.y, s0.z + s1.z, s0.w + s1.w);

    __shared__ float4 red[256];
    red[t] = s;
    __syncthreads();
    if (hs == 0) {
        float4 a = red[t], b1 = red[t + 64], c1 = red[t + 128], d = red[t + 192];
        a.x += b1.x + c1.x + d.x;
        a.y += b1.y + c1.y + d.y;
        a.z += b1.z + c1.z + d.z;
        a.w += b1.w + c1.w + d.w;
        __stcs(&((float4*)g_part)[(size_t)bcq * (W_ / 4) + w4], a);   // coalesced
    }
}

// ---------------------------------------------------------------------------
// Kernel 2: gating MLP + memory-bank attention. 256 blocks; block = (b, 8 w).
// Stages its 256(cq) x 8(w) partial tile through padded smem (transpose),
// then one warp per row runs the verified warp-per-row math.
// ---------------------------------------------------------------------------
__global__ __launch_bounds__(256) void gate_kernel(
    const float* __restrict__ w_sub, const float* __restrict__ b_sub,
    const float* __restrict__ w_up,  const float* __restrict__ b_up,
    const float* __restrict__ mb,    const float* __restrict__ mu)
{
    __shared__ float s_wsub[C_ * LD_];
    __shared__ float s_mb[LD_ * MEM_];
    __shared__ float s_wup[LD_ * C_];
    __shared__ float s_bsub[LD_];
    __shared__ float s_bup[C_];
    __shared__ float tile[8 * TP_];       // [wl][cq], padded

    const int tid = threadIdx.x;
    for (int i = tid; i < C_ * LD_;   i += blockDim.x) s_wsub[i] = w_sub[i];
    for (int i = tid; i < LD_ * MEM_; i += blockDim.x) s_mb[i]   = mb[i];
    for (int i = tid; i < LD_ * C_;   i += blockDim.x) s_wup[i]  = w_up[i];
    if (tid < LD_) s_bsub[tid] = b_sub[tid];
    if (tid < C_)  s_bup[tid]  = b_up[tid];

    const int b  = blockIdx.x >> 5;            // batch
    const int w8 = (blockIdx.x & 31) * 8;      // w slice start

    // Stage + transpose: 256 rows x 8 cols; thread (cq-group, wl).
#pragma unroll
    for (int it = 0; it < 8; ++it) {
        const int cq = (tid >> 3) + 32 * it;
        const int wl = tid & 7;
        tile[wl * TP_ + cq] = g_part[((size_t)b * CQ_ + cq) * W_ + w8 + wl];
    }
    __syncthreads();

    const float muv   = mu[0];
    const float inv_h = 1.0f / H_;
    const float scale = rsqrtf((float)LD_);

    const int wp   = tid >> 5;                 // warp -> row
    const int lane = tid & 31;
    const int w    = w8 + wp;
    const float* tr = tile + wp * TP_;

    float yA = 0.f, yB = 0.f;
#pragma unroll
    for (int q = 0; q < NQ_; ++q) {
        yA += tr[lane * 4 + q];
        yB += tr[(lane + 32) * 4 + q];
    }
    yA *= inv_h; yB *= inv_h;

    float low[LD_];
#pragma unroll
    for (int j = 0; j < LD_; ++j) {
        float p = fmaf(yA, s_wsub[lane * LD_ + j],
                       yB * s_wsub[(lane + 32) * LD_ + j]);
#pragma unroll
        for (int off = 16; off > 0; off >>= 1)
            p += __shfl_xor_sync(0xffffffffu, p, off);
        low[j] = p + s_bsub[j];
    }

    float f1[4];
#pragma unroll
    for (int k = 0; k < 4; ++k) {
        const int m = lane + 32 * k;
        float acc = 0.f;
#pragma unroll
        for (int j = 0; j < LD_; ++j)
            acc = fmaf(low[j], s_mb[j * MEM_ + m], acc);
        f1[k] = acc * scale;
    }

    float mx = fmaxf(fmaxf(f1[0], f1[1]), fmaxf(f1[2], f1[3]));
#pragma unroll
    for (int off = 16; off > 0; off >>= 1)
        mx = fmaxf(mx, __shfl_xor_sync(0xffffffffu, mx, off));
    float e[4], sum = 0.f;
#pragma unroll
    for (int k = 0; k < 4; ++k) { e[k] = expf(f1[k] - mx); sum += e[k]; }
#pragma unroll
    for (int off = 16; off > 0; off >>= 1)
        sum += __shfl_xor_sync(0xffffffffu, sum, off);
    const float inv = 1.0f / sum;

    float y1[LD_];
#pragma unroll
    for (int j = 0; j < LD_; ++j) {
        float acc = 0.f;
#pragma unroll
        for (int k = 0; k < 4; ++k)
            acc = fmaf(e[k] * inv, s_mb[j * MEM_ + lane + 32 * k], acc);
#pragma unroll
        for (int off = 16; off > 0; off >>= 1)
            acc += __shfl_xor_sync(0xffffffffu, acc, off);
        y1[j] = acc;
    }

#pragma unroll
    for (int k = 0; k < 2; ++k) {
        const int c = lane + 32 * k;
        float acc = s_bup[c];
#pragma unroll
        for (int j = 0; j < LD_; ++j)
            acc = fmaf(y1[j], s_wup[j * C_ + c], acc);
        const float g = 1.0f / (1.0f + expf(-acc));
        g_gateT[(size_t)(b * C_ + c) * W_ + w] = g * muv;
    }
}

// ---------------------------------------------------------------------------
// Kernel 3: out = x * gate. Fixed float4 column per thread (gate = one reg).
// Batch-4 loads, minblocks 6 (occupancy fix), __ldcs/__stcs (measured-good).
// ---------------------------------------------------------------------------
__global__ __launch_bounds__(256, 6) void apply_gate_kernel(
    const float* __restrict__ x, float* __restrict__ out)
{
    const int bcq = (NBLK_ - 1) - blockIdx.x;   // reverse order: L2 reuse
    const int bc  = bcq >> 2;
    const int q   = bcq & (NQ_ - 1);

    const int t   = threadIdx.x;
    const int w4  = t & 63;
    const int hs  = t >> 6;

    const float4 gv = __ldg(&((const float4*)(g_gateT + (size_t)bc * W_))[w4]);

    const size_t base = (size_t)bc * (H_ * W_) + (size_t)q * HCHUNK_ * W_;
    const float4* __restrict__ xp = (const float4*)(x + base);
    float4*       __restrict__ op = (float4*)(out + base);

#pragma unroll
    for (int quarter = 0; quarter < 4; ++quarter) {
        float4 v[4];
#pragma unroll
        for (int k = 0; k < 4; ++k)
            v[k] = __ldcs(&xp[(size_t)(hs + 4 * (quarter * 4 + k)) * (W_ / 4) + w4]);
#pragma unroll
        for (int k = 0; k < 4; ++k) {
            v[k].x *= gv.x; v[k].y *= gv.y; v[k].z *= gv.z; v[k].w *= gv.w;
            __stcs(&op[(size_t)(hs + 4 * (quarter * 4 + k)) * (W_ / 4) + w4], v[k]);
        }
    }
}

extern "C" void kernel_launch(void* const* d_in, const int* in_sizes, int n_in,
                              void* d_out, int out_size) {
    const float* x     = (const float*)d_in[0];
    const float* w_sub = (const float*)d_in[1];
    const float* b_sub = (const float*)d_in[2];
    const float* w_up  = (const float*)d_in[3];
    const float* b_up  = (const float*)d_in[4];
    const float* mb    = (const float*)d_in[5];
    const float* mu    = (const float*)d_in[6];
    float* out = (float*)d_out;

    reduce_h_partial_kernel<<<NBLK_, 256>>>(x);
    gate_kernel<<<256, 256>>>(w_sub, b_sub, w_up, b_up, mb, mu);
    apply_gate_kernel<<<NBLK_, 256>>>(x, out);
}

// round 12
// speedup vs baseline: 1.0492x; 1.0098x over previous
#include <cuda_runtime.h>
#include <math.h>

#define B_   8
#define C_   64
#define H_   256
#define W_   256
#define LD_  8
#define MEM_ 128
#define NROWS_ (B_ * W_)    // 2048
#define HCHUNK_ 64          // h rows per reduce/apply block
#define NQ_ (H_ / HCHUNK_)  // 4 chunks per plane
#define NBLK_ (B_ * C_ * NQ_)  // 2048
#define CQ_ (C_ * NQ_)      // 256 partial rows per batch
#define TP_  257            // padded transpose stride

// Scratch (allocation-free per harness rules)
__device__ float g_part[NBLK_ * W_];     // partials [b][c*4+q][w], coalesced (2 MB)
__device__ float g_gateT[B_ * C_ * W_];  // gate*mu, [bc][w] (0.5 MB)

// ---------------------------------------------------------------------------
// Kernel 1: partial sum over a 64-row h-chunk of one (b,c) plane.
// Coalesced float4 partial store (measured 23.2-23.5us / ~75% DRAM).
// ---------------------------------------------------------------------------
__global__ __launch_bounds__(256) void reduce_h_partial_kernel(const float* __restrict__ x) {
    const int bcq = blockIdx.x;           // = b*256 + (c*4+q)
    const int t  = threadIdx.x;
    const int w4 = t & 63;                // float4 column 0..63
    const int hs = t >> 6;                // h-subgroup 0..3

    const float4* __restrict__ xp =
        (const float4*)(x + (size_t)(bcq >> 2) * (H_ * W_) +
                        (size_t)(bcq & (NQ_ - 1)) * HCHUNK_ * W_);

    float4 s0 = make_float4(0.f, 0.f, 0.f, 0.f);
    float4 s1 = make_float4(0.f, 0.f, 0.f, 0.f);

#pragma unroll
    for (int half = 0; half < 2; ++half) {
        float4 v[8];
#pragma unroll
        for (int k = 0; k < 8; ++k)
            v[k] = xp[(size_t)(hs + 4 * (half * 8 + k)) * (W_ / 4) + w4];
#pragma unroll
        for (int k = 0; k < 8; ++k) {
            if (k & 1) { s1.x += v[k].x; s1.y += v[k].y; s1.z += v[k].z; s1.w += v[k].w; }
            else       { s0.x += v[k].x; s0.y += v[k].y; s0.z += v[k].z; s0.w += v[k].w; }
        }
    }
    float4 s = make_float4(s0.x + s1.x, s0.y + s1.y, s0.z + s1.z, s0.w + s1.w);

    __shared__ float4 red[256];
    red[t] = s;
    __syncthreads();
    if (hs == 0) {
        float4 a = red[t], b1 = red[t + 64], c1 = red[t + 128], d = red[t + 192];
        a.x += b1.x + c1.x + d.x;
        a.y += b1.y + c1.y + d.y;
        a.z += b1.z + c1.z + d.z;
        a.w += b1.w + c1.w + d.w;
        __stcs(&((float4*)g_part)[(size_t)bcq * (W_ / 4) + w4], a);   // coalesced
    }
}

// ---------------------------------------------------------------------------
// Kernel 2: gating MLP + memory-bank attention. 256 blocks; block = (b, 8 w).
// Stages its 256(cq) x 8(w) partial tile through padded smem (transpose),
// then one warp per row runs the verified warp-per-row math.
// ---------------------------------------------------------------------------
__global__ __launch_bounds__(256) void gate_kernel(
    const float* __restrict__ w_sub, const float* __restrict__ b_sub,
    const float* __restrict__ w_up,  const float* __restrict__ b_up,
    const float* __restrict__ mb,    const float* __restrict__ mu)
{
    __shared__ float s_wsub[C_ * LD_];
    __shared__ float s_mb[LD_ * MEM_];
    __shared__ float s_wup[LD_ * C_];
    __shared__ float s_bsub[LD_];
    __shared__ float s_bup[C_];
    __shared__ float tile[8 * TP_];       // [wl][cq], padded

    const int tid = threadIdx.x;
    for (int i = tid; i < C_ * LD_;   i += blockDim.x) s_wsub[i] = w_sub[i];
    for (int i = tid; i < LD_ * MEM_; i += blockDim.x) s_mb[i]   = mb[i];
    for (int i = tid; i < LD_ * C_;   i += blockDim.x) s_wup[i]  = w_up[i];
    if (tid < LD_) s_bsub[tid] = b_sub[tid];
    if (tid < C_)  s_bup[tid]  = b_up[tid];

    const int b  = blockIdx.x >> 5;            // batch
    const int w8 = (blockIdx.x & 31) * 8;      // w slice start

    // Stage + transpose: 256 rows x 8 cols; thread (cq-group, wl).
#pragma unroll
    for (int it = 0; it < 8; ++it) {
        const int cq = (tid >> 3) + 32 * it;
        const int wl = tid & 7;
        tile[wl * TP_ + cq] = g_part[((size_t)b * CQ_ + cq) * W_ + w8 + wl];
    }
    __syncthreads();

    const float muv   = mu[0];
    const float inv_h = 1.0f / H_;
    const float scale = rsqrtf((float)LD_);

    const int wp   = tid >> 5;                 // warp -> row
    const int lane = tid & 31;
    const int w    = w8 + wp;
    const float* tr = tile + wp * TP_;

    float yA = 0.f, yB = 0.f;
#pragma unroll
    for (int q = 0; q < NQ_; ++q) {
        yA += tr[lane * 4 + q];
        yB += tr[(lane + 32) * 4 + q];
    }
    yA *= inv_h; yB *= inv_h;

    float low[LD_];
#pragma unroll
    for (int j = 0; j < LD_; ++j) {
        float p = fmaf(yA, s_wsub[lane * LD_ + j],
                       yB * s_wsub[(lane + 32) * LD_ + j]);
#pragma unroll
        for (int off = 16; off > 0; off >>= 1)
            p += __shfl_xor_sync(0xffffffffu, p, off);
        low[j] = p + s_bsub[j];
    }

    float f1[4];
#pragma unroll
    for (int k = 0; k < 4; ++k) {
        const int m = lane + 32 * k;
        float acc = 0.f;
#pragma unroll
        for (int j = 0; j < LD_; ++j)
            acc = fmaf(low[j], s_mb[j * MEM_ + m], acc);
        f1[k] = acc * scale;
    }

    float mx = fmaxf(fmaxf(f1[0], f1[1]), fmaxf(f1[2], f1[3]));
#pragma unroll
    for (int off = 16; off > 0; off >>= 1)
        mx = fmaxf(mx, __shfl_xor_sync(0xffffffffu, mx, off));
    float e[4], sum = 0.f;
#pragma unroll
    for (int k = 0; k < 4; ++k) { e[k] = expf(f1[k] - mx); sum += e[k]; }
#pragma unroll
    for (int off = 16; off > 0; off >>= 1)
        sum += __shfl_xor_sync(0xffffffffu, sum, off);
    const float inv = 1.0f / sum;

    float y1[LD_];
#pragma unroll
    for (int j = 0; j < LD_; ++j) {
        float acc = 0.f;
#pragma unroll
        for (int k = 0; k < 4; ++k)
            acc = fmaf(e[k] * inv, s_mb[j * MEM_ + lane + 32 * k], acc);
#pragma unroll
        for (int off = 16; off > 0; off >>= 1)
            acc += __shfl_xor_sync(0xffffffffu, acc, off);
        y1[j] = acc;
    }

#pragma unroll
    for (int k = 0; k < 2; ++k) {
        const int c = lane + 32 * k;
        float acc = s_bup[c];
#pragma unroll
        for (int j = 0; j < LD_; ++j)
            acc = fmaf(y1[j], s_wup[j * C_ + c], acc);
        const float g = 1.0f / (1.0f + expf(-acc));
        g_gateT[(size_t)(b * C_ + c) * W_ + w] = g * muv;
    }
}

// ---------------------------------------------------------------------------
// Kernel 3: out = x * gate. EXACT R8 form (measured 36.8us): fixed float4
// column per thread, 8-deep load batches, __ldcs/__stcs, reverse block order,
// no minblocks cap (regs ~66, occ 32% — but deeper per-thread MLP wins).
// ---------------------------------------------------------------------------
__global__ __launch_bounds__(256) void apply_gate_kernel(
    const float* __restrict__ x, float* __restrict__ out)
{
    const int bcq = (NBLK_ - 1) - blockIdx.x;   // reverse order
    const int bc  = bcq >> 2;
    const int q   = bcq & (NQ_ - 1);

    const int t   = threadIdx.x;
    const int w4  = t & 63;
    const int hs  = t >> 6;

    const float4 gv = __ldg(&((const float4*)(g_gateT + (size_t)bc * W_))[w4]);

    const size_t base = (size_t)bc * (H_ * W_) + (size_t)q * HCHUNK_ * W_;
    const float4* __restrict__ xp = (const float4*)(x + base);
    float4*       __restrict__ op = (float4*)(out + base);

#pragma unroll
    for (int half = 0; half < 2; ++half) {
        float4 v[8];
#pragma unroll
        for (int k = 0; k < 8; ++k)
            v[k] = __ldcs(&xp[(size_t)(hs + 4 * (half * 8 + k)) * (W_ / 4) + w4]);
#pragma unroll
        for (int k = 0; k < 8; ++k) {
            v[k].x *= gv.x; v[k].y *= gv.y; v[k].z *= gv.z; v[k].w *= gv.w;
            __stcs(&op[(size_t)(hs + 4 * (half * 8 + k)) * (W_ / 4) + w4], v[k]);
        }
    }
}

extern "C" void kernel_launch(void* const* d_in, const int* in_sizes, int n_in,
                              void* d_out, int out_size) {
    const float* x     = (const float*)d_in[0];
    const float* w_sub = (const float*)d_in[1];
    const float* b_sub = (const float*)d_in[2];
    const float* w_up  = (const float*)d_in[3];
    const float* b_up  = (const float*)d_in[4];
    const float* mb    = (const float*)d_in[5];
    const float* mu    = (const float*)d_in[6];
    float* out = (float*)d_out;

    reduce_h_partial_kernel<<<NBLK_, 256>>>(x);
    gate_kernel<<<256, 256>>>(w_sub, b_sub, w_up, b_up, mb, mu);
    apply_gate_kernel<<<NBLK_, 256>>>(x, out);
}

// round 13
// speedup vs baseline: 1.0764x; 1.0259x over previous
#include <cuda_runtime.h>
#include <math.h>

#define B_   8
#define C_   64
#define H_   256
#define W_   256
#define LD_  8
#define MEM_ 128
#define NROWS_ (B_ * W_)      // 2048
// reduce: single-wave config
#define HCH_R 128             // h rows per reduce block
#define NQR_  (H_ / HCH_R)    // 2 chunks per plane
#define RBLK_ (B_ * C_ * NQR_)  // 1024 reduce blocks (single wave)
#define CQ_   (C_ * NQR_)     // 128 partial rows per batch
#define TP_   (CQ_ + 1)       // 129, padded transpose stride
// apply: R12 config
#define HCH_A 64
#define NQA_  (H_ / HCH_A)    // 4
#define ABLK_ (B_ * C_ * NQA_)  // 2048

// Scratch (allocation-free per harness rules)
__device__ float g_part[RBLK_ * W_];     // partials [b][c*2+q][w], coalesced (1 MB)
__device__ float g_gateT[B_ * C_ * W_];  // gate*mu, [bc][w] (0.5 MB)

// ---------------------------------------------------------------------------
// Kernel 1: partial sum over a 128-row h-chunk of one (b,c) plane.
// Grid 1024 = SINGLE WAVE (~7 blocks/SM): no wave-quantization tail.
// 32 float4 loads per thread in 4 batches of 8 (deep MLP).
// ---------------------------------------------------------------------------
__global__ __launch_bounds__(256) void reduce_h_partial_kernel(const float* __restrict__ x) {
    const int bcq = blockIdx.x;           // = (b*C+c)*2 + q
    const int t  = threadIdx.x;
    const int w4 = t & 63;                // float4 column 0..63
    const int hs = t >> 6;                // h-subgroup 0..3

    const float4* __restrict__ xp =
        (const float4*)(x + (size_t)(bcq >> 1) * (H_ * W_) +
                        (size_t)(bcq & 1) * HCH_R * W_);

    float4 s0 = make_float4(0.f, 0.f, 0.f, 0.f);
    float4 s1 = make_float4(0.f, 0.f, 0.f, 0.f);

#pragma unroll
    for (int grp = 0; grp < 4; ++grp) {
        float4 v[8];
#pragma unroll
        for (int k = 0; k < 8; ++k)
            v[k] = xp[(size_t)(hs + 4 * (grp * 8 + k)) * (W_ / 4) + w4];
#pragma unroll
        for (int k = 0; k < 8; ++k) {
            if (k & 1) { s1.x += v[k].x; s1.y += v[k].y; s1.z += v[k].z; s1.w += v[k].w; }
            else       { s0.x += v[k].x; s0.y += v[k].y; s0.z += v[k].z; s0.w += v[k].w; }
        }
    }
    float4 s = make_float4(s0.x + s1.x, s0.y + s1.y, s0.z + s1.z, s0.w + s1.w);

    __shared__ float4 red[256];
    red[t] = s;
    __syncthreads();
    if (hs == 0) {
        float4 a = red[t], b1 = red[t + 64], c1 = red[t + 128], d = red[t + 192];
        a.x += b1.x + c1.x + d.x;
        a.y += b1.y + c1.y + d.y;
        a.z += b1.z + c1.z + d.z;
        a.w += b1.w + c1.w + d.w;
        __stcs(&((float4*)g_part)[(size_t)bcq * (W_ / 4) + w4], a);   // coalesced
    }
}

// ---------------------------------------------------------------------------
// Kernel 2: gating MLP + memory-bank attention. 256 blocks; block = (b, 8 w).
// Stages its 128(cq) x 8(w) partial tile through padded smem (transpose),
// then one warp per row runs the verified warp-per-row math.
// ---------------------------------------------------------------------------
__global__ __launch_bounds__(256) void gate_kernel(
    const float* __restrict__ w_sub, const float* __restrict__ b_sub,
    const float* __restrict__ w_up,  const float* __restrict__ b_up,
    const float* __restrict__ mb,    const float* __restrict__ mu)
{
    __shared__ float s_wsub[C_ * LD_];
    __shared__ float s_mb[LD_ * MEM_];
    __shared__ float s_wup[LD_ * C_];
    __shared__ float s_bsub[LD_];
    __shared__ float s_bup[C_];
    __shared__ float tile[8 * TP_];       // [wl][cq], padded

    const int tid = threadIdx.x;
    for (int i = tid; i < C_ * LD_;   i += blockDim.x) s_wsub[i] = w_sub[i];
    for (int i = tid; i < LD_ * MEM_; i += blockDim.x) s_mb[i]   = mb[i];
    for (int i = tid; i < LD_ * C_;   i += blockDim.x) s_wup[i]  = w_up[i];
    if (tid < LD_) s_bsub[tid] = b_sub[tid];
    if (tid < C_)  s_bup[tid]  = b_up[tid];

    const int b  = blockIdx.x >> 5;            // batch
    const int w8 = (blockIdx.x & 31) * 8;      // w slice start

    // Stage + transpose: 128 rows x 8 cols; thread (cq-group, wl).
#pragma unroll
    for (int it = 0; it < 4; ++it) {
        const int cq = (tid >> 3) + 32 * it;
        const int wl = tid & 7;
        tile[wl * TP_ + cq] = g_part[((size_t)b * CQ_ + cq) * W_ + w8 + wl];
    }
    __syncthreads();

    const float muv   = mu[0];
    const float inv_h = 1.0f / H_;
    const float scale = rsqrtf((float)LD_);

    const int wp   = tid >> 5;                 // warp -> row
    const int lane = tid & 31;
    const int w    = w8 + wp;
    const float* tr = tile + wp * TP_;

    // y[c] for c = lane, lane+32 (2 q-partials each, from smem)
    const float yA = (tr[lane * 2] + tr[lane * 2 + 1]) * inv_h;
    const float yB = (tr[(lane + 32) * 2] + tr[(lane + 32) * 2 + 1]) * inv_h;

    float low[LD_];
#pragma unroll
    for (int j = 0; j < LD_; ++j) {
        float p = fmaf(yA, s_wsub[lane * LD_ + j],
                       yB * s_wsub[(lane + 32) * LD_ + j]);
#pragma unroll
        for (int off = 16; off > 0; off >>= 1)
            p += __shfl_xor_sync(0xffffffffu, p, off);
        low[j] = p + s_bsub[j];
    }

    float f1[4];
#pragma unroll
    for (int k = 0; k < 4; ++k) {
        const int m = lane + 32 * k;
        float acc = 0.f;
#pragma unroll
        for (int j = 0; j < LD_; ++j)
            acc = fmaf(low[j], s_mb[j * MEM_ + m], acc);
        f1[k] = acc * scale;
    }

    float mx = fmaxf(fmaxf(f1[0], f1[1]), fmaxf(f1[2], f1[3]));
#pragma unroll
    for (int off = 16; off > 0; off >>= 1)
        mx = fmaxf(mx, __shfl_xor_sync(0xffffffffu, mx, off));
    float e[4], sum = 0.f;
#pragma unroll
    for (int k = 0; k < 4; ++k) { e[k] = expf(f1[k] - mx); sum += e[k]; }
#pragma unroll
    for (int off = 16; off > 0; off >>= 1)
        sum += __shfl_xor_sync(0xffffffffu, sum, off);
    const float inv = 1.0f / sum;

    float y1[LD_];
#pragma unroll
    for (int j = 0; j < LD_; ++j) {
        float acc = 0.f;
#pragma unroll
        for (int k = 0; k < 4; ++k)
            acc = fmaf(e[k] * inv, s_mb[j * MEM_ + lane + 32 * k], acc);
#pragma unroll
        for (int off = 16; off > 0; off >>= 1)
            acc += __shfl_xor_sync(0xffffffffu, acc, off);
        y1[j] = acc;
    }

#pragma unroll
    for (int k = 0; k < 2; ++k) {
        const int c = lane + 32 * k;
        float acc = s_bup[c];
#pragma unroll
        for (int j = 0; j < LD_; ++j)
            acc = fmaf(y1[j], s_wup[j * C_ + c], acc);
        const float g = 1.0f / (1.0f + expf(-acc));
        g_gateT[(size_t)(b * C_ + c) * W_ + w] = g * muv;
    }
}

// ---------------------------------------------------------------------------
// Kernel 3: out = x * gate. EXACT R12 form (best measured total): fixed float4
// column per thread, 8-deep load batches, __ldcs/__stcs, reverse block order.
// ---------------------------------------------------------------------------
__global__ __launch_bounds__(256) void apply_gate_kernel(
    const float* __restrict__ x, float* __restrict__ out)
{
    const int bcq = (ABLK_ - 1) - blockIdx.x;   // reverse order
    const int bc  = bcq >> 2;
    const int q   = bcq & (NQA_ - 1);

    const int t   = threadIdx.x;
    const int w4  = t & 63;
    const int hs  = t >> 6;

    const float4 gv = __ldg(&((const float4*)(g_gateT + (size_t)bc * W_))[w4]);

    const size_t base = (size_t)bc * (H_ * W_) + (size_t)q * HCH_A * W_;
    const float4* __restrict__ xp = (const float4*)(x + base);
    float4*       __restrict__ op = (float4*)(out + base);

#pragma unroll
    for (int half = 0; half < 2; ++half) {
        float4 v[8];
#pragma unroll
        for (int k = 0; k < 8; ++k)
            v[k] = __ldcs(&xp[(size_t)(hs + 4 * (half * 8 + k)) * (W_ / 4) + w4]);
#pragma unroll
        for (int k = 0; k < 8; ++k) {
            v[k].x *= gv.x; v[k].y *= gv.y; v[k].z *= gv.z; v[k].w *= gv.w;
            __stcs(&op[(size_t)(hs + 4 * (half * 8 + k)) * (W_ / 4) + w4], v[k]);
        }
    }
}

extern "C" void kernel_launch(void* const* d_in, const int* in_sizes, int n_in,
                              void* d_out, int out_size) {
    const float* x     = (const float*)d_in[0];
    const float* w_sub = (const float*)d_in[1];
    const float* b_sub = (const float*)d_in[2];
    const float* w_up  = (const float*)d_in[3];
    const float* b_up  = (const float*)d_in[4];
    const float* mb    = (const float*)d_in[5];
    const float* mu    = (const float*)d_in[6];
    float* out = (float*)d_out;

    reduce_h_partial_kernel<<<RBLK_, 256>>>(x);
    gate_kernel<<<256, 256>>>(w_sub, b_sub, w_up, b_up, mb, mu);
    apply_gate_kernel<<<ABLK_, 256>>>(x, out);
}